// round 13
// baseline (speedup 1.0000x reference)
#include <cuda_runtime.h>
#include <cstdint>

#define NC 16
#define HW (512*512)
#define NB 8
#define M (NB*HW)
#define HBLK 256
#define TPX 512
#define NTILES (M / TPX)       // 4096
#define GRID 444               // 148 SMs * 3 CTAs @ 69KB smem

// dynamic smem layout (bytes)
#define OFF_L    0             // float s_l[2][NC][TPX]   : 65536
#define OFF_LAB  65536         // int   s_lab[2][TPX]     : 4096
#define SMEM_DYN 69632

__device__ double       g_acc[2];
__device__ unsigned int g_done;
__device__ unsigned int g_hdone;
__device__ unsigned int g_tile = GRID;     // stealing cursor; reset at end
__device__ float        g_part[HBLK * NC];
__device__ float        g_cc[NC];

__device__ __forceinline__ int iget(const int4& v, int j) {
    return j == 0 ? v.x : j == 1 ? v.y : j == 2 ? v.z : v.w;
}
__device__ __forceinline__ void cp16(uint32_t dst, const void* src) {
    asm volatile("cp.async.cg.shared.global [%0], [%1], 16;" :: "r"(dst), "l"(src));
}

// ------------------------------------------------ histogram + last-block reduce
__global__ void __launch_bounds__(256) k_hist(const int4* __restrict__ labels,
                                              const float* __restrict__ cums) {
    int lane = threadIdx.x & 31;
    int w    = threadIdx.x >> 5;
    int cnt = 0;
    int idx    = blockIdx.x * blockDim.x + threadIdx.x;
    int stride = gridDim.x * blockDim.x;
    for (int i = idx; i < M / 4; i += stride) {
        int4 lb = labels[i];
        #pragma unroll
        for (int k = 0; k < 4; k++) {
            int lab = iget(lb, k);
            #pragma unroll
            for (int c = 0; c < NC; c++) {
                unsigned mb = __ballot_sync(0xFFFFFFFFu, lab == c);
                if (lane == c) cnt += __popc(mb);
            }
        }
    }
    __shared__ int sm[8 * NC];
    if (lane < NC) sm[w * NC + lane] = cnt;
    __syncthreads();
    int t = threadIdx.x;
    if (t < NC) {
        int tot = 0;
        #pragma unroll
        for (int i = 0; i < 8; i++) tot += sm[i * NC + t];
        g_part[blockIdx.x * NC + t] = (float)tot;
    }
    __shared__ bool is_last;
    __threadfence();
    __syncthreads();
    if (t == 0) is_last = (atomicAdd(&g_hdone, 1u) == HBLK - 1);
    __syncthreads();
    if (is_last) {
        __shared__ float sr[256];
        int c  = t & 15;
        int r0 = t >> 4;
        float sum = 0.f;
        #pragma unroll
        for (int k = 0; k < HBLK / 16; k++)
            sum += g_part[(r0 + k * 16) * NC + c];
        sr[t] = sum;
        __syncthreads();
        if (t < NC) {
            float tot = 0.f;
            #pragma unroll
            for (int r = 0; r < 16; r++) tot += sr[r * NC + t];
            g_cc[t] = fmaxf(cums[t] + tot, 1.0f);
        }
        if (t == 0) g_hdone = 0u;
        __threadfence();
    }
}

// ------------------------------------------------ pipelined main (512px tiles)
__global__ void __launch_bounds__(256) k_main(const float* __restrict__ cls,
                                              const int*   __restrict__ labels,
                                              float*       __restrict__ out) {
    extern __shared__ char dyn[];
    float (*s_l)[NC][TPX] = (float (*)[NC][TPX])(dyn + OFF_L);
    int   (*s_lab)[TPX]   = (int (*)[TPX])(dyn + OFF_LAB);
    __shared__ float smit[NC * NC];       // transposed: smit[c*16+lab]
    __shared__ int   s_next[2];
    __shared__ float rn[8], rm[8];

    int tid  = threadIdx.x;
    int lane = tid & 31;
    int wrp  = tid >> 5;
    {
        int labi = tid & 15;
        int ci   = tid >> 4;
        float ratio = g_cc[ci] / g_cc[labi];
        smit[tid] = (ratio < 1.0f) ? __powf(ratio, 0.8f) : 1.0f;
    }

    uint32_t sl_base  = (uint32_t)__cvta_generic_to_shared(dyn + OFF_L);
    uint32_t slab_base= (uint32_t)__cvta_generic_to_shared(dyn + OFF_LAB);
    const char* cbase = (const char*)cls;
    const char* lbase = (const char*)labels;

    int ch0  = tid >> 7;                       // 0..1
    int part = tid & 127;                      // 0..127 (16B chunks of a 2KB row)
    uint32_t goff = (uint32_t)ch0 * (HW * 4u) + (uint32_t)part * 16u;   // per-thread
    uint32_t soff = (uint32_t)ch0 * 2048u + (uint32_t)part * 16u;

    auto issue = [&](int tile, int bi) {
        // tile*TPX: b = tile>>9, hw = (tile&511)<<9 px -> bytes <<11 (all 32-bit)
        uint32_t toff = (uint32_t)(tile >> 9) * (NC * HW * 4u)
                      + ((uint32_t)(tile & 511) << 11);
        const char* src = cbase + (toff + goff);
        uint32_t dst = sl_base + (uint32_t)bi * 32768u + soff;
        #pragma unroll
        for (int k = 0; k < 8; k++)            // channels ch0, ch0+2, ..., ch0+14
            cp16(dst + (uint32_t)k * 4096u, src + (uint32_t)k * (2u * HW * 4u));
        if (tid < 128)
            cp16(slab_base + (uint32_t)bi * 2048u + (uint32_t)tid * 16u,
                 lbase + (uint32_t)tile * 2048u + (uint32_t)tid * 16u);
        asm volatile("cp.async.commit_group;");
    };

    issue(blockIdx.x, 0);
    if (tid == 0) s_next[0] = atomicAdd(&g_tile, 1);

    float nll = 0.f, msk = 0.f;
    int t_cur = blockIdx.x;
    int buf = 0;
    while (t_cur < NTILES) {
        __syncthreads();                   // s_next[buf] (+smit first pass); buf^1 free
        int t_nxt = s_next[buf];
        if (t_nxt < NTILES) {
            issue(t_nxt, buf ^ 1);
            if (tid == 0) s_next[buf ^ 1] = atomicAdd(&g_tile, 1);
            asm volatile("cp.async.wait_group 1;");
        } else {
            asm volatile("cp.async.wait_group 0;");
        }
        __syncthreads();                   // buf data ready

        #pragma unroll
        for (int j = 0; j < 2; j++) {
            int px  = tid + j * 256;
            int lab = s_lab[buf][px];

            float e[NC];
            float s = 0.f;
            #pragma unroll
            for (int c = 0; c < NC; c++) {
                float ec = __expf(s_l[buf][c][px]);   // conflict-free LDS
                e[c] = ec;
                s += ec;
            }
            float l_lab = s_l[buf][lab][px];          // dynamic LDS, bank = px%32
            float selfE = __expf(l_lab);
            float inv = __fdividef(1.0f, fmaxf(selfE, 0.01f * s));

            float sum2 = 0.f;
            #pragma unroll
            for (int c = 0; c < NC; c++) {
                float tt = fmaxf(e[c] * inv, 1.0f);
                float es = e[c] * smit[(c << 4) + lab];
                sum2 = fmaf(es, tt * tt, sum2);
            }

            if (lab != 0) {
                nll += __logf(sum2) - l_lab;          // ln(selfE) == l_lab exactly
                msk += 1.f;
            }
        }
        t_cur = t_nxt;
        buf ^= 1;
    }

    // block reduction + finalize
    #pragma unroll
    for (int o = 16; o > 0; o >>= 1) {
        nll += __shfl_down_sync(0xFFFFFFFFu, nll, o);
        msk += __shfl_down_sync(0xFFFFFFFFu, msk, o);
    }
    if (lane == 0) { rn[wrp] = nll; rm[wrp] = msk; }
    __syncthreads();
    if (tid == 0) {
        float a = 0.f, bs = 0.f;
        #pragma unroll
        for (int i = 0; i < 8; i++) { a += rn[i]; bs += rm[i]; }
        atomicAdd(&g_acc[0], (double)a);
        atomicAdd(&g_acc[1], (double)bs);
        __threadfence();
        unsigned v = atomicAdd(&g_done, 1u);
        if (v == GRID - 1) {               // last block: finalize + reset
            __threadfence();
            out[0] = (float)(g_acc[0] / g_acc[1]);
            g_acc[0] = 0.0;
            g_acc[1] = 0.0;
            g_done   = 0u;
            g_tile   = GRID;
        }
    }
}

extern "C" void kernel_launch(void* const* d_in, const int* in_sizes, int n_in,
                              void* d_out, int out_size) {
    const float* cls    = (const float*)d_in[0];
    const int*   labels = (const int*)  d_in[1];
    const float* cums   = (const float*)d_in[2];
    float* out = (float*)d_out;

    static bool attr_set = false;
    if (!attr_set) {
        cudaFuncSetAttribute(k_main, cudaFuncAttributeMaxDynamicSharedMemorySize,
                             SMEM_DYN);
        attr_set = true;
    }

    k_hist<<<HBLK, 256>>>((const int4*)labels, cums);
    k_main<<<GRID, 256, SMEM_DYN>>>(cls, labels, out);
}

// round 14
// speedup vs baseline: 1.1934x; 1.1934x over previous
#include <cuda_runtime.h>
#include <cstdint>

#define NC 16
#define HW (512*512)
#define NB 8
#define M (NB*HW)
#define HBLK 256
#define WT 64                     // pixels per warp-tile
#define NWT (M / WT)              // 32768
#define GRID 444                  // 148 * 3 CTAs (smem-limited)
#define NWARPS (GRID * 8)         // 3552

// dynamic smem layout (bytes): [warp][buf][ch][64px] then labels
#define SL_BYTES   65536          // 8 warps * 2 bufs * 16ch * 64px * 4B
#define OFF_LAB    65536          // 8 warps * 2 bufs * 64px * 4B = 4096
#define SMEM_DYN   69632

__device__ double       g_acc[2];
__device__ unsigned int g_done;
__device__ unsigned int g_hdone;
__device__ float        g_part[HBLK * NC];
__device__ float        g_cc[NC];

typedef unsigned long long ull;

__device__ __forceinline__ int iget(const int4& v, int j) {
    return j == 0 ? v.x : j == 1 ? v.y : j == 2 ? v.z : v.w;
}
__device__ __forceinline__ void cp16(uint32_t dst, const void* src) {
    asm volatile("cp.async.cg.shared.global [%0], [%1], 16;" :: "r"(dst), "l"(src));
}
__device__ __forceinline__ ull pk(float a, float b) {
    ull r; asm("mov.b64 %0, {%1, %2};" : "=l"(r) : "f"(a), "f"(b)); return r;
}
__device__ __forceinline__ void upk(ull v, float& a, float& b) {
    asm("mov.b64 {%0, %1}, %2;" : "=f"(a), "=f"(b) : "l"(v));
}
__device__ __forceinline__ ull mul2(ull a, ull b) {
    ull r; asm("mul.rn.f32x2 %0, %1, %2;" : "=l"(r) : "l"(a), "l"(b)); return r;
}
__device__ __forceinline__ ull add2(ull a, ull b) {
    ull r; asm("add.rn.f32x2 %0, %1, %2;" : "=l"(r) : "l"(a), "l"(b)); return r;
}
__device__ __forceinline__ ull fma2(ull a, ull b, ull c) {
    ull r; asm("fma.rn.f32x2 %0, %1, %2, %3;" : "=l"(r) : "l"(a), "l"(b), "l"(c)); return r;
}
__device__ __forceinline__ float ex2f(float x) {
    float r; asm("ex2.approx.f32 %0, %1;" : "=f"(r) : "f"(x)); return r;
}

// ------------------------------------------------ histogram + last-block reduce
__global__ void __launch_bounds__(256) k_hist(const int4* __restrict__ labels,
                                              const float* __restrict__ cums) {
    int lane = threadIdx.x & 31;
    int w    = threadIdx.x >> 5;
    int cnt = 0;
    int idx    = blockIdx.x * blockDim.x + threadIdx.x;
    int stride = gridDim.x * blockDim.x;
    for (int i = idx; i < M / 4; i += stride) {
        int4 lb = labels[i];
        #pragma unroll
        for (int k = 0; k < 4; k++) {
            int lab = iget(lb, k);
            #pragma unroll
            for (int c = 0; c < NC; c++) {
                unsigned mb = __ballot_sync(0xFFFFFFFFu, lab == c);
                if (lane == c) cnt += __popc(mb);
            }
        }
    }
    __shared__ int sm[8 * NC];
    if (lane < NC) sm[w * NC + lane] = cnt;
    __syncthreads();
    int t = threadIdx.x;
    if (t < NC) {
        int tot = 0;
        #pragma unroll
        for (int i = 0; i < 8; i++) tot += sm[i * NC + t];
        g_part[blockIdx.x * NC + t] = (float)tot;
    }
    __shared__ bool is_last;
    __threadfence();
    __syncthreads();
    if (t == 0) is_last = (atomicAdd(&g_hdone, 1u) == HBLK - 1);
    __syncthreads();
    if (is_last) {
        __shared__ float sr[256];
        int c  = t & 15;
        int r0 = t >> 4;
        float sum = 0.f;
        #pragma unroll
        for (int k = 0; k < HBLK / 16; k++)
            sum += g_part[(r0 + k * 16) * NC + c];
        sr[t] = sum;
        __syncthreads();
        if (t < NC) {
            float tot = 0.f;
            #pragma unroll
            for (int r = 0; r < 16; r++) tot += sr[r * NC + t];
            g_cc[t] = fmaxf(cums[t] + tot, 1.0f);
        }
        if (t == 0) g_hdone = 0u;
        __threadfence();
    }
}

// ------------------------------------------------ per-warp pipelined main, f32x2
__global__ void __launch_bounds__(256, 3) k_main(const float* __restrict__ cls,
                                                 const int*   __restrict__ labels,
                                                 float*       __restrict__ out) {
    extern __shared__ char dyn[];
    __shared__ float smit[NC * NC];       // transposed: smit[c*16+lab]
    __shared__ float rn[8], rm[8];

    int tid  = threadIdx.x;
    int lane = tid & 31;
    int wrp  = tid >> 5;
    {
        int labi = tid & 15;
        int ci   = tid >> 4;
        float ratio = g_cc[ci] / g_cc[labi];
        smit[tid] = (ratio < 1.0f) ? __powf(ratio, 0.8f) : 1.0f;
    }
    __syncthreads();                       // only block barrier before steady loop

    uint32_t sl_base   = (uint32_t)__cvta_generic_to_shared(dyn) + (uint32_t)(wrp * 8192);
    uint32_t slab_base = (uint32_t)__cvta_generic_to_shared(dyn + OFF_LAB) + (uint32_t)(wrp * 512);
    const char* cbase = (const char*)cls;
    const char* lbase = (const char*)labels;
    int hi   = lane >> 4;                  // 0/1
    int part = lane & 15;

    auto issue = [&](int t, int bi) {
        uint32_t toff = (uint32_t)(t >> 12) * (NC * HW * 4u)
                      + ((uint32_t)(t & 4095) << 8);          // tile*64px*4B
        const char* src0 = cbase + toff + (uint32_t)hi * (HW * 4u) + (uint32_t)part * 16u;
        uint32_t dst0 = sl_base + (uint32_t)(bi * 4096 + hi * 256 + part * 16);
        #pragma unroll
        for (int k = 0; k < 8; k++)        // channels hi, hi+2, ..., hi+14
            cp16(dst0 + (uint32_t)k * 512u, src0 + (uint32_t)k * (2u * HW * 4u));
        if (lane < 16)
            cp16(slab_base + (uint32_t)(bi * 256 + lane * 16),
                 lbase + (uint32_t)t * 256u + (uint32_t)lane * 16u);
        asm volatile("cp.async.commit_group;");
    };

    const ull LOG2E2 = pk(1.4426950408889634f, 1.4426950408889634f);
    const int g = blockIdx.x * 8 + wrp;    // global warp id
    int px0 = lane * 2;

    if (g < NWT) issue(g, 0);

    float nll = 0.f, msk = 0.f;
    int buf = 0;
    for (int t = g; t < NWT; t += NWARPS) {
        int nxt = t + NWARPS;
        if (nxt < NWT) {
            issue(nxt, buf ^ 1);
            asm volatile("cp.async.wait_group 1;");
        } else {
            asm volatile("cp.async.wait_group 0;");
        }
        __syncwarp();                      // all lanes' groups complete

        const float* tl   = (const float*)(dyn + wrp * 8192 + buf * 4096); // [ch][64]
        const int*   tlab = (const int*)(dyn + OFF_LAB + wrp * 512 + buf * 256);

        // pass 1: packed exp over the pixel pair
        ull e2[NC];
        ull s2 = pk(0.f, 0.f);
        #pragma unroll
        for (int c = 0; c < NC; c++) {
            float2 lv = *(const float2*)(tl + c * WT + px0);   // LDS.64, conflict-free
            ull t2 = mul2(pk(lv.x, lv.y), LOG2E2);
            float ta, tb; upk(t2, ta, tb);
            e2[c] = pk(ex2f(ta), ex2f(tb));
            s2 = add2(s2, e2[c]);
        }
        float sa, sb; upk(s2, sa, sb);

        int lab0 = tlab[px0], lab1 = tlab[px0 + 1];
        float ll0 = tl[lab0 * WT + px0];          // dynamic LDS (2-way max)
        float ll1 = tl[lab1 * WT + px0 + 1];
        float se0 = ex2f(ll0 * 1.4426950408889634f);
        float se1 = ex2f(ll1 * 1.4426950408889634f);
        float inv0 = __fdividef(1.f, fmaxf(se0, 0.01f * sa));
        float inv1 = __fdividef(1.f, fmaxf(se1, 0.01f * sb));
        ull inv2 = pk(inv0, inv1);

        // pass 2: packed weighted sum
        ull acc = pk(0.f, 0.f);
        #pragma unroll
        for (int c = 0; c < NC; c++) {
            ull r2 = mul2(e2[c], inv2);
            float ra, rb; upk(r2, ra, rb);
            ull tt = pk(fmaxf(ra, 1.f), fmaxf(rb, 1.f));
            ull sm2 = pk(smit[(c << 4) + lab0], smit[(c << 4) + lab1]);
            acc = fma2(mul2(e2[c], sm2), mul2(tt, tt), acc);
        }
        float s20, s21; upk(acc, s20, s21);

        if (lab0 != 0) { nll += __logf(s20) - ll0; msk += 1.f; }
        if (lab1 != 0) { nll += __logf(s21) - ll1; msk += 1.f; }

        __syncwarp();                      // done reading buf before refill
        buf ^= 1;
    }

    // block reduction + finalize
    #pragma unroll
    for (int o = 16; o > 0; o >>= 1) {
        nll += __shfl_down_sync(0xFFFFFFFFu, nll, o);
        msk += __shfl_down_sync(0xFFFFFFFFu, msk, o);
    }
    if (lane == 0) { rn[wrp] = nll; rm[wrp] = msk; }
    __syncthreads();
    if (tid == 0) {
        float a = 0.f, bs = 0.f;
        #pragma unroll
        for (int i = 0; i < 8; i++) { a += rn[i]; bs += rm[i]; }
        atomicAdd(&g_acc[0], (double)a);
        atomicAdd(&g_acc[1], (double)bs);
        __threadfence();
        unsigned v = atomicAdd(&g_done, 1u);
        if (v == GRID - 1) {               // last block: finalize + reset
            __threadfence();
            out[0] = (float)(g_acc[0] / g_acc[1]);
            g_acc[0] = 0.0;
            g_acc[1] = 0.0;
            g_done   = 0u;
        }
    }
}

extern "C" void kernel_launch(void* const* d_in, const int* in_sizes, int n_in,
                              void* d_out, int out_size) {
    const float* cls    = (const float*)d_in[0];
    const int*   labels = (const int*)  d_in[1];
    const float* cums   = (const float*)d_in[2];
    float* out = (float*)d_out;

    static bool attr_set = false;
    if (!attr_set) {
        cudaFuncSetAttribute(k_main, cudaFuncAttributeMaxDynamicSharedMemorySize,
                             SMEM_DYN);
        attr_set = true;
    }

    k_hist<<<HBLK, 256>>>((const int4*)labels, cums);
    k_main<<<GRID, 256, SMEM_DYN>>>(cls, labels, out);
}